// round 15
// baseline (speedup 1.0000x reference)
#include <cuda_runtime.h>
#include <cstdint>
#include <cstddef>

typedef unsigned long long u64;
typedef ulonglong2 ull2;

#define T_LEN 1024
#define HID   256
#define BGN   4        // batch groups
#define HGN   32       // hidden groups (CTAs per batch group)
#define BC    32       // batch rows per CTA
#define UC    8        // hidden units per CTA
#define NTHR  256

#define WSZ   (3*UC*HID)          // one W slice: 24 rows x 256
#define TSZ   (BC*HID)            // activation tile: 32 rows x 256
#define SMEM_FLOATS (4*WSZ + 3*TSZ)
#define SMEM_BYTES  (SMEM_FLOATS*4)   // 196608 B

// persistent device state (allocation-free)
__device__ u64   g_flag[BGN * HGN];
__device__ float g_h0[128 * HID];
__device__ float g_h1[128 * HID];

// ---------------------------------------------------------------------------
__device__ __forceinline__ void ffma2(u64& a, u64 b, u64 c) {
    asm("fma.rn.f32x2 %0, %1, %2, %0;" : "+l"(a) : "l"(b), "l"(c));
}
__device__ __forceinline__ float us(u64 v) {
    float lo, hi;
    asm("mov.b64 {%0,%1}, %2;" : "=f"(lo), "=f"(hi) : "l"(v));
    return lo + hi;
}
__device__ __forceinline__ u64 ldacq(const u64* p) {
    u64 v;
    asm volatile("ld.acquire.gpu.u64 %0, [%1];" : "=l"(v) : "l"(p) : "memory");
    return v;
}
__device__ __forceinline__ void strel(u64* p, u64 v) {
    asm volatile("st.release.gpu.u64 [%0], %1;" :: "l"(p), "l"(v) : "memory");
}
__device__ __forceinline__ float sigm(float v) { return 1.0f / (1.0f + __expf(-v)); }
__device__ __forceinline__ float tanh_(float v) {
    float e = __expf(-2.0f * fabsf(v));
    return copysignf((1.0f - e) / (1.0f + e), v);
}
__device__ __forceinline__ int swz(int g) { return g ^ ((g >> 3) & 7); }

__device__ __forceinline__ void waitflag(const u64* f, u64 tgt) {
    while (ldacq(f) < tgt) __nanosleep(16);
}

// ---------------------------------------------------------------------------
// SMEM fills (granule-swizzled). Weight slice rows: lr = gate*8 + unit_local.
// ---------------------------------------------------------------------------
__device__ __forceinline__ void fill_w(float* sw, const float* __restrict__ W,
                                       int hg, int tid) {
    for (int i = tid; i < 3 * UC * 64; i += NTHR) {
        int lr = i >> 6, q = i & 63;
        int g = lr >> 3, u = lr & 7;
        float4 v = __ldg((const float4*)(W + (size_t)(g * HID + hg * UC + u) * HID) + q);
        *(float4*)(sw + lr * HID + swz(q) * 4) = v;
    }
}

// activation tiles: thread (br = tid>>3, c = tid&7) owns granules c*8 .. c*8+7
__device__ __forceinline__ void pref_x(float4* xr, const float* __restrict__ x,
                                       int bg, int t, int tid) {
    int br = tid >> 3, c = tid & 7;
    const float4* s =
        (const float4*)(x + ((size_t)(bg * BC + br) * T_LEN + t) * HID) + c * 8;
#pragma unroll
    for (int i = 0; i < 8; ++i) xr[i] = __ldcg(s + i);
}
__device__ __forceinline__ void store_x(const float4* xr, float* sx, int tid) {
    int br = tid >> 3, c = tid & 7;
    float* d = sx + br * HID;
#pragma unroll
    for (int i = 0; i < 8; ++i) *(float4*)(d + swz(c * 8 + i) * 4) = xr[i];
}
__device__ __forceinline__ void load_tile(float* dst, const float* __restrict__ gsrc,
                                          int bg, int tid) {
    int br = tid >> 3, c = tid & 7;
    const float4* s = (const float4*)(gsrc + (size_t)(bg * BC + br) * HID) + c * 8;
    float4 v[8];
#pragma unroll
    for (int i = 0; i < 8; ++i) v[i] = __ldcg(s + i);
    float* d = dst + br * HID;
#pragma unroll
    for (int i = 0; i < 8; ++i) *(float4*)(d + swz(c * 8 + i) * 4) = v[i];
}

// ---------------------------------------------------------------------------
// One GRU layer phase for this thread:
//   unit e (global), K-slice ks (16 floats), rows wb*16 .. wb*16+15.
// Weights for the phase pulled from SMEM into registers ONCE (24 ull2),
// then 4 chunks of 4 rows: 8 act LDS + 24 ffma2 per row, butterfly-reduce
// 16 partials across the 16 ks lanes, finalize+store on lanes ks<4.
// ---------------------------------------------------------------------------
__device__ __forceinline__ void do_phase(
    const float* __restrict__ sA, const float* __restrict__ sB,
    const float* __restrict__ sWx, const float* __restrict__ sWh,
    float br, float bz, float bxn, float bhn,
    float* __restrict__ gdst,        // g_h base for this bg (row-local indexing)
    int e, int u_loc, int wb, int ks, int lane)
{
    // ---- load this phase's weight K-slices into registers ----
    ull2 wx[12], wh[12];
#pragma unroll
    for (int g = 0; g < 3; ++g)
#pragma unroll
        for (int i = 0; i < 4; ++i) {
            const int off = 4 * swz(ks * 4 + i);
            wx[g * 4 + i] = *(const ull2*)(sWx + (g * 8 + u_loc) * HID + off);
            wh[g * 4 + i] = *(const ull2*)(sWh + (g * 8 + u_loc) * HID + off);
        }

#pragma unroll
    for (int chunk = 0; chunk < 4; ++chunk) {
        const int rowbase = wb * 16 + chunk * 4;
        u64 aR[4], aZ[4], aX[4], aH[4];
#pragma unroll
        for (int r = 0; r < 4; ++r) { aR[r] = 0; aZ[r] = 0; aX[r] = 0; aH[r] = 0; }
#pragma unroll
        for (int r = 0; r < 4; ++r) {
            const float* pa = sA + (rowbase + r) * HID;
            const float* pb = sB + (rowbase + r) * HID;
#pragma unroll
            for (int i = 0; i < 4; ++i) {
                const int off = 4 * swz(ks * 4 + i);
                ull2 xa = *(const ull2*)(pa + off);
                ull2 xb = *(const ull2*)(pb + off);
                ffma2(aR[r], wx[i].x,     xa.x); ffma2(aR[r], wx[i].y,     xa.y);
                ffma2(aR[r], wh[i].x,     xb.x); ffma2(aR[r], wh[i].y,     xb.y);
                ffma2(aZ[r], wx[4 + i].x, xa.x); ffma2(aZ[r], wx[4 + i].y, xa.y);
                ffma2(aZ[r], wh[4 + i].x, xb.x); ffma2(aZ[r], wh[4 + i].y, xb.y);
                ffma2(aX[r], wx[8 + i].x, xa.x); ffma2(aX[r], wx[8 + i].y, xa.y);
                ffma2(aH[r], wh[8 + i].x, xb.x); ffma2(aH[r], wh[8 + i].y, xb.y);
            }
        }
        // ---- 16-value butterfly across the 16 ks lanes ----
        float v[16];
#pragma unroll
        for (int r = 0; r < 4; ++r) {
            v[r] = us(aR[r]); v[4 + r] = us(aZ[r]);
            v[8 + r] = us(aX[r]); v[12 + r] = us(aH[r]);
        }
#pragma unroll
        for (int c = 0; c < 8; ++c) {
            float k = (ks & 8) ? v[c + 8] : v[c], s = (ks & 8) ? v[c] : v[c + 8];
            v[c] = k + __shfl_xor_sync(0xffffffffu, s, 8);
        }
#pragma unroll
        for (int c = 0; c < 4; ++c) {
            float k = (ks & 4) ? v[c + 4] : v[c], s = (ks & 4) ? v[c] : v[c + 4];
            v[c] = k + __shfl_xor_sync(0xffffffffu, s, 4);
        }
#pragma unroll
        for (int c = 0; c < 2; ++c) {
            float k = (ks & 2) ? v[c + 2] : v[c], s = (ks & 2) ? v[c] : v[c + 2];
            v[c] = k + __shfl_xor_sync(0xffffffffu, s, 2);
        }
        float k0 = (ks & 1) ? v[1] : v[0], s0 = (ks & 1) ? v[0] : v[1];
        float tot = k0 + __shfl_xor_sync(0xffffffffu, s0, 1);
        // lane ks holds value idx ks: 0-3 = R rows, 4-7 = Z, 8-11 = X, 12-15 = H
        const int gb = lane & 16;
        float Zv = __shfl_sync(0xffffffffu, tot, gb + 4  + (lane & 3));
        float Xv = __shfl_sync(0xffffffffu, tot, gb + 8  + (lane & 3));
        float Hv = __shfl_sync(0xffffffffu, tot, gb + 12 + (lane & 3));
        if (ks < 4) {
            const int row = rowbase + ks;
            float hold = sB[row * HID + 4 * swz(e >> 2) + (e & 3)];
            float rr = sigm(tot + br);
            float zz = sigm(Zv + bz);
            float nn = tanh_(Xv + bxn + rr * (Hv + bhn));
            gdst[(size_t)row * HID + e] = zz * hold + (1.0f - zz) * nn;
        }
    }
}

// ---------------------------------------------------------------------------
__global__ void __launch_bounds__(NTHR, 1)
gru_persistent(const float* __restrict__ x,
               const float* __restrict__ Wx0, const float* __restrict__ bx0,
               const float* __restrict__ Wh0, const float* __restrict__ bh0,
               const float* __restrict__ Wx1, const float* __restrict__ bx1,
               const float* __restrict__ Wh1, const float* __restrict__ bh1,
               const float* __restrict__ Wo,  const float* __restrict__ bo,
               float* __restrict__ out)
{
    extern __shared__ float sm[];
    float* sWx0 = sm;
    float* sWh0 = sWx0 + WSZ;
    float* sWx1 = sWh0 + WSZ;
    float* sWh1 = sWx1 + WSZ;
    float* sx   = sWh1 + WSZ;
    float* sh0  = sx  + TSZ;
    float* sh1  = sh0 + TSZ;

    const int tid  = threadIdx.x;
    const int bg   = blockIdx.x >> 5;
    const int hg   = blockIdx.x & 31;
    const int warp = tid >> 5;
    const int lane = tid & 31;
    const int up   = warp & 3;           // unit pair
    const int wb   = warp >> 2;          // row half: rows [wb*16, wb*16+16)
    const int uu   = lane >> 4;          // unit within pair
    const int ks   = lane & 15;          // K-slice [ks*16, ks*16+16)
    const int u_loc = up * 2 + uu;       // local unit 0..7
    const int e     = hg * UC + u_loc;   // global unit

    fill_w(sWx0, Wx0, hg, tid);
    fill_w(sWh0, Wh0, hg, tid);
    fill_w(sWx1, Wx1, hg, tid);
    fill_w(sWh1, Wh1, hg, tid);
    for (int i = tid; i < TSZ; i += NTHR) { sh0[i] = 0.0f; sh1[i] = 0.0f; }
    {
        float4 xr[8];
        pref_x(xr, x, bg, 0, tid);
        store_x(xr, sx, tid);
    }
    __syncthreads();

    const float br0  = bx0[e] + bh0[e];
    const float bz0  = bx0[HID + e] + bh0[HID + e];
    const float bxn0 = bx0[2 * HID + e], bhn0 = bh0[2 * HID + e];
    const float br1  = bx1[e] + bh1[e];
    const float bz1  = bx1[HID + e] + bh1[HID + e];
    const float bxn1 = bx1[2 * HID + e], bhn1 = bh1[2 * HID + e];

    float* gdst0 = g_h0 + (size_t)(bg * BC) * HID;
    float* gdst1 = g_h1 + (size_t)(bg * BC) * HID;

    u64* myflag = &g_flag[bg * HGN + hg];
    const u64 base = ldacq(myflag);

    for (int t = 0; t < T_LEN; ++t) {
        // ================= phase A: layer 0 =================
        do_phase(sx, sh0, sWx0, sWh0, br0, bz0, bxn0, bhn0,
                 gdst0, e, u_loc, wb, ks, lane);
        __threadfence();
        __syncthreads();
        if (tid == 0) strel(myflag, base + (u64)(2 * t + 1));

        float4 xr[8];
        if (t + 1 < T_LEN) pref_x(xr, x, bg, t + 1, tid);   // overlap with wait

        if (tid < HGN) waitflag(&g_flag[bg * HGN + tid], base + (u64)(2 * t + 1));
        __syncthreads();
        load_tile(sh0, g_h0, bg, tid);
        if (t + 1 < T_LEN) store_x(xr, sx, tid);
        __syncthreads();

        // ================= phase B: layer 1 =================
        do_phase(sh0, sh1, sWx1, sWh1, br1, bz1, bxn1, bhn1,
                 gdst1, e, u_loc, wb, ks, lane);
        __threadfence();
        __syncthreads();
        if (tid == 0) strel(myflag, base + (u64)(2 * t + 2));

        if (tid < HGN) waitflag(&g_flag[bg * HGN + tid], base + (u64)(2 * t + 2));
        __syncthreads();
        load_tile(sh1, g_h1, bg, tid);
        __syncthreads();
    }

    // ---- output projection: out = h1 @ Wo.T + bo (hg<16 covers 128 cols) ----
    if (hg < 16) {
        const int b = tid >> 3, o8 = tid & 7;
        const int o = hg * 8 + o8;
        const float* ph = sh1 + b * HID;
        const ull2* wo = (const ull2*)(Wo + (size_t)o * HID);
        u64 a0 = 0, a1 = 0;
#pragma unroll 8
        for (int g = 0; g < 64; ++g) {
            ull2 hv = *(const ull2*)(ph + swz(g) * 4);
            ull2 wv = __ldg(wo + g);
            ffma2(a0, wv.x, hv.x);
            ffma2(a1, wv.y, hv.y);
        }
        out[(size_t)(bg * BC + b) * 128 + o] = us(a0) + us(a1) + __ldg(bo + o);
    }
}

// ---------------------------------------------------------------------------
extern "C" void kernel_launch(void* const* d_in, const int* in_sizes, int n_in,
                              void* d_out, int out_size) {
    (void)in_sizes; (void)n_in; (void)out_size;
    const float* x   = (const float*)d_in[0];
    const float* Wx0 = (const float*)d_in[1];
    const float* bx0 = (const float*)d_in[2];
    const float* Wh0 = (const float*)d_in[3];
    const float* bh0 = (const float*)d_in[4];
    const float* Wx1 = (const float*)d_in[5];
    const float* bx1 = (const float*)d_in[6];
    const float* Wh1 = (const float*)d_in[7];
    const float* bh1 = (const float*)d_in[8];
    const float* Wo  = (const float*)d_in[9];
    const float* bo  = (const float*)d_in[10];
    float* out = (float*)d_out;

    cudaFuncSetAttribute(gru_persistent,
                         cudaFuncAttributeMaxDynamicSharedMemorySize, SMEM_BYTES);
    gru_persistent<<<BGN * HGN, NTHR, SMEM_BYTES>>>(
        x, Wx0, bx0, Wh0, bh0, Wx1, bx1, Wh1, bh1, Wo, bo, out);
}

// round 16
// speedup vs baseline: 1.0460x; 1.0460x over previous
#include <cuda_runtime.h>
#include <cstdint>
#include <cstddef>

typedef unsigned long long u64;
typedef ulonglong2 ull2;

#define T_LEN 1024
#define HID   256
#define BGN   4        // batch groups
#define HGN   32       // hidden groups (CTAs per batch group)
#define BC    32       // batch rows per CTA
#define UC    8        // hidden units per CTA
#define NTHR  256

#define WSZ   (3*UC*HID)          // one W slice: 24 rows x 256
#define TSZ   (BC*HID)            // activation tile: 32 rows x 256
#define SMEM_FLOATS (4*WSZ + 3*TSZ)
#define SMEM_BYTES  (SMEM_FLOATS*4)   // 196608 B

// persistent device state (allocation-free)
__device__ u64   g_flag[BGN * HGN];
__device__ float g_h0[128 * HID];
__device__ float g_h1[128 * HID];

// ---------------------------------------------------------------------------
__device__ __forceinline__ void ffma2(u64& a, u64 b, u64 c) {
    asm("fma.rn.f32x2 %0, %1, %2, %0;" : "+l"(a) : "l"(b), "l"(c));
}
__device__ __forceinline__ float us(u64 v) {
    float lo, hi;
    asm("mov.b64 {%0,%1}, %2;" : "=f"(lo), "=f"(hi) : "l"(v));
    return lo + hi;
}
__device__ __forceinline__ u64 ldacq(const u64* p) {
    u64 v;
    asm volatile("ld.acquire.gpu.u64 %0, [%1];" : "=l"(v) : "l"(p) : "memory");
    return v;
}
__device__ __forceinline__ void strel(u64* p, u64 v) {
    asm volatile("st.release.gpu.u64 [%0], %1;" :: "l"(p), "l"(v) : "memory");
}
__device__ __forceinline__ float sigm(float v) { return 1.0f / (1.0f + __expf(-v)); }
__device__ __forceinline__ float tanh_(float v) {
    float e = __expf(-2.0f * fabsf(v));
    return copysignf((1.0f - e) / (1.0f + e), v);
}
__device__ __forceinline__ int swz(int g) { return g ^ ((g >> 3) & 7); }

__device__ __forceinline__ void waitflag(const u64* f, u64 tgt) {
    while (ldacq(f) < tgt) __nanosleep(16);
}

// ---------------------------------------------------------------------------
// SMEM fills (granule-swizzled). Weight slice rows: lr = gate*8 + unit_local.
// ---------------------------------------------------------------------------
__device__ __forceinline__ void fill_w(float* sw, const float* __restrict__ W,
                                       int hg, int tid) {
    for (int i = tid; i < 3 * UC * 64; i += NTHR) {
        int lr = i >> 6, q = i & 63;
        int g = lr >> 3, u = lr & 7;
        float4 v = __ldg((const float4*)(W + (size_t)(g * HID + hg * UC + u) * HID) + q);
        *(float4*)(sw + lr * HID + swz(q) * 4) = v;
    }
}

// activation tiles: thread (br = tid>>3, c = tid&7) owns granules c*8 .. c*8+7
__device__ __forceinline__ void pref_x(float4* xr, const float* __restrict__ x,
                                       int bg, int t, int tid) {
    int br = tid >> 3, c = tid & 7;
    const float4* s =
        (const float4*)(x + ((size_t)(bg * BC + br) * T_LEN + t) * HID) + c * 8;
#pragma unroll
    for (int i = 0; i < 8; ++i) xr[i] = __ldcg(s + i);
}
__device__ __forceinline__ void store_x(const float4* xr, float* sx, int tid) {
    int br = tid >> 3, c = tid & 7;
    float* d = sx + br * HID;
#pragma unroll
    for (int i = 0; i < 8; ++i) *(float4*)(d + swz(c * 8 + i) * 4) = xr[i];
}
__device__ __forceinline__ void load_tile(float* dst, const float* __restrict__ gsrc,
                                          int bg, int tid) {
    int br = tid >> 3, c = tid & 7;
    const float4* s = (const float4*)(gsrc + (size_t)(bg * BC + br) * HID) + c * 8;
    float4 v[8];
#pragma unroll
    for (int i = 0; i < 8; ++i) v[i] = __ldcg(s + i);
    float* d = dst + br * HID;
#pragma unroll
    for (int i = 0; i < 8; ++i) *(float4*)(d + swz(c * 8 + i) * 4) = v[i];
}

// ---------------------------------------------------------------------------
// One GRU layer phase for this thread:
//   unit e (global), K-slice ks (16 floats), rows wb*16 .. wb*16+15.
// Weights for the phase pulled from SMEM into registers ONCE (24 ull2),
// then 4 chunks of 4 rows: 8 act LDS + 24 ffma2 per row, butterfly-reduce
// 16 partials across the 16 ks lanes, finalize+store on lanes ks<4.
// ---------------------------------------------------------------------------
__device__ __forceinline__ void do_phase(
    const float* __restrict__ sA, const float* __restrict__ sB,
    const float* __restrict__ sWx, const float* __restrict__ sWh,
    float br, float bz, float bxn, float bhn,
    float* __restrict__ gdst,        // g_h base for this bg (row-local indexing)
    int e, int u_loc, int wb, int ks, int lane)
{
    // ---- load this phase's weight K-slices into registers ----
    ull2 wx[12], wh[12];
#pragma unroll
    for (int g = 0; g < 3; ++g)
#pragma unroll
        for (int i = 0; i < 4; ++i) {
            const int off = 4 * swz(ks * 4 + i);
            wx[g * 4 + i] = *(const ull2*)(sWx + (g * 8 + u_loc) * HID + off);
            wh[g * 4 + i] = *(const ull2*)(sWh + (g * 8 + u_loc) * HID + off);
        }

#pragma unroll
    for (int chunk = 0; chunk < 4; ++chunk) {
        const int rowbase = wb * 16 + chunk * 4;
        u64 aR[4], aZ[4], aX[4], aH[4];
#pragma unroll
        for (int r = 0; r < 4; ++r) { aR[r] = 0; aZ[r] = 0; aX[r] = 0; aH[r] = 0; }
#pragma unroll
        for (int r = 0; r < 4; ++r) {
            const float* pa = sA + (rowbase + r) * HID;
            const float* pb = sB + (rowbase + r) * HID;
#pragma unroll
            for (int i = 0; i < 4; ++i) {
                const int off = 4 * swz(ks * 4 + i);
                ull2 xa = *(const ull2*)(pa + off);
                ull2 xb = *(const ull2*)(pb + off);
                ffma2(aR[r], wx[i].x,     xa.x); ffma2(aR[r], wx[i].y,     xa.y);
                ffma2(aR[r], wh[i].x,     xb.x); ffma2(aR[r], wh[i].y,     xb.y);
                ffma2(aZ[r], wx[4 + i].x, xa.x); ffma2(aZ[r], wx[4 + i].y, xa.y);
                ffma2(aZ[r], wh[4 + i].x, xb.x); ffma2(aZ[r], wh[4 + i].y, xb.y);
                ffma2(aX[r], wx[8 + i].x, xa.x); ffma2(aX[r], wx[8 + i].y, xa.y);
                ffma2(aH[r], wh[8 + i].x, xb.x); ffma2(aH[r], wh[8 + i].y, xb.y);
            }
        }
        // ---- 16-value butterfly across the 16 ks lanes ----
        float v[16];
#pragma unroll
        for (int r = 0; r < 4; ++r) {
            v[r] = us(aR[r]); v[4 + r] = us(aZ[r]);
            v[8 + r] = us(aX[r]); v[12 + r] = us(aH[r]);
        }
#pragma unroll
        for (int c = 0; c < 8; ++c) {
            float k = (ks & 8) ? v[c + 8] : v[c], s = (ks & 8) ? v[c] : v[c + 8];
            v[c] = k + __shfl_xor_sync(0xffffffffu, s, 8);
        }
#pragma unroll
        for (int c = 0; c < 4; ++c) {
            float k = (ks & 4) ? v[c + 4] : v[c], s = (ks & 4) ? v[c] : v[c + 4];
            v[c] = k + __shfl_xor_sync(0xffffffffu, s, 4);
        }
#pragma unroll
        for (int c = 0; c < 2; ++c) {
            float k = (ks & 2) ? v[c + 2] : v[c], s = (ks & 2) ? v[c] : v[c + 2];
            v[c] = k + __shfl_xor_sync(0xffffffffu, s, 2);
        }
        float k0 = (ks & 1) ? v[1] : v[0], s0 = (ks & 1) ? v[0] : v[1];
        float tot = k0 + __shfl_xor_sync(0xffffffffu, s0, 1);
        // lane ks holds value idx ks: 0-3 = R rows, 4-7 = Z, 8-11 = X, 12-15 = H
        const int gb = lane & 16;
        float Zv = __shfl_sync(0xffffffffu, tot, gb + 4  + (lane & 3));
        float Xv = __shfl_sync(0xffffffffu, tot, gb + 8  + (lane & 3));
        float Hv = __shfl_sync(0xffffffffu, tot, gb + 12 + (lane & 3));
        if (ks < 4) {
            const int row = rowbase + ks;
            float hold = sB[row * HID + 4 * swz(e >> 2) + (e & 3)];
            float rr = sigm(tot + br);
            float zz = sigm(Zv + bz);
            float nn = tanh_(Xv + bxn + rr * (Hv + bhn));
            gdst[(size_t)row * HID + e] = zz * hold + (1.0f - zz) * nn;
        }
    }
}

// ---------------------------------------------------------------------------
__global__ void __launch_bounds__(NTHR, 1)
gru_persistent(const float* __restrict__ x,
               const float* __restrict__ Wx0, const float* __restrict__ bx0,
               const float* __restrict__ Wh0, const float* __restrict__ bh0,
               const float* __restrict__ Wx1, const float* __restrict__ bx1,
               const float* __restrict__ Wh1, const float* __restrict__ bh1,
               const float* __restrict__ Wo,  const float* __restrict__ bo,
               float* __restrict__ out)
{
    extern __shared__ float sm[];
    float* sWx0 = sm;
    float* sWh0 = sWx0 + WSZ;
    float* sWx1 = sWh0 + WSZ;
    float* sWh1 = sWx1 + WSZ;
    float* sx   = sWh1 + WSZ;
    float* sh0  = sx  + TSZ;
    float* sh1  = sh0 + TSZ;

    const int tid  = threadIdx.x;
    const int bg   = blockIdx.x >> 5;
    const int hg   = blockIdx.x & 31;
    const int warp = tid >> 5;
    const int lane = tid & 31;
    const int up   = warp & 3;           // unit pair
    const int wb   = warp >> 2;          // row half: rows [wb*16, wb*16+16)
    const int uu   = lane >> 4;          // unit within pair
    const int ks   = lane & 15;          // K-slice [ks*16, ks*16+16)
    const int u_loc = up * 2 + uu;       // local unit 0..7
    const int e     = hg * UC + u_loc;   // global unit

    fill_w(sWx0, Wx0, hg, tid);
    fill_w(sWh0, Wh0, hg, tid);
    fill_w(sWx1, Wx1, hg, tid);
    fill_w(sWh1, Wh1, hg, tid);
    for (int i = tid; i < TSZ; i += NTHR) { sh0[i] = 0.0f; sh1[i] = 0.0f; }
    {
        float4 xr[8];
        pref_x(xr, x, bg, 0, tid);
        store_x(xr, sx, tid);
    }
    __syncthreads();

    const float br0  = bx0[e] + bh0[e];
    const float bz0  = bx0[HID + e] + bh0[HID + e];
    const float bxn0 = bx0[2 * HID + e], bhn0 = bh0[2 * HID + e];
    const float br1  = bx1[e] + bh1[e];
    const float bz1  = bx1[HID + e] + bh1[HID + e];
    const float bxn1 = bx1[2 * HID + e], bhn1 = bh1[2 * HID + e];

    float* gdst0 = g_h0 + (size_t)(bg * BC) * HID;
    float* gdst1 = g_h1 + (size_t)(bg * BC) * HID;

    u64* myflag = &g_flag[bg * HGN + hg];
    const u64 base = ldacq(myflag);

    for (int t = 0; t < T_LEN; ++t) {
        // ================= phase A: layer 0 =================
        do_phase(sx, sh0, sWx0, sWh0, br0, bz0, bxn0, bhn0,
                 gdst0, e, u_loc, wb, ks, lane);
        __threadfence();
        __syncthreads();
        if (tid == 0) strel(myflag, base + (u64)(2 * t + 1));

        float4 xr[8];
        if (t + 1 < T_LEN) pref_x(xr, x, bg, t + 1, tid);   // overlap with wait

        if (tid < HGN) waitflag(&g_flag[bg * HGN + tid], base + (u64)(2 * t + 1));
        __syncthreads();
        load_tile(sh0, g_h0, bg, tid);
        if (t + 1 < T_LEN) store_x(xr, sx, tid);
        __syncthreads();

        // ================= phase B: layer 1 =================
        do_phase(sh0, sh1, sWx1, sWh1, br1, bz1, bxn1, bhn1,
                 gdst1, e, u_loc, wb, ks, lane);
        __threadfence();
        __syncthreads();
        if (tid == 0) strel(myflag, base + (u64)(2 * t + 2));

        if (tid < HGN) waitflag(&g_flag[bg * HGN + tid], base + (u64)(2 * t + 2));
        __syncthreads();
        load_tile(sh1, g_h1, bg, tid);
        __syncthreads();
    }

    // ---- output projection: out = h1 @ Wo.T + bo (hg<16 covers 128 cols) ----
    if (hg < 16) {
        const int b = tid >> 3, o8 = tid & 7;
        const int o = hg * 8 + o8;
        const float* ph = sh1 + b * HID;
        const ull2* wo = (const ull2*)(Wo + (size_t)o * HID);
        u64 a0 = 0, a1 = 0;
#pragma unroll 8
        for (int g = 0; g < 64; ++g) {
            ull2 hv = *(const ull2*)(ph + swz(g) * 4);
            ull2 wv = __ldg(wo + g);
            ffma2(a0, wv.x, hv.x);
            ffma2(a1, wv.y, hv.y);
        }
        out[(size_t)(bg * BC + b) * 128 + o] = us(a0) + us(a1) + __ldg(bo + o);
    }
}

// ---------------------------------------------------------------------------
extern "C" void kernel_launch(void* const* d_in, const int* in_sizes, int n_in,
                              void* d_out, int out_size) {
    (void)in_sizes; (void)n_in; (void)out_size;
    const float* x   = (const float*)d_in[0];
    const float* Wx0 = (const float*)d_in[1];
    const float* bx0 = (const float*)d_in[2];
    const float* Wh0 = (const float*)d_in[3];
    const float* bh0 = (const float*)d_in[4];
    const float* Wx1 = (const float*)d_in[5];
    const float* bx1 = (const float*)d_in[6];
    const float* Wh1 = (const float*)d_in[7];
    const float* bh1 = (const float*)d_in[8];
    const float* Wo  = (const float*)d_in[9];
    const float* bo  = (const float*)d_in[10];
    float* out = (float*)d_out;

    cudaFuncSetAttribute(gru_persistent,
                         cudaFuncAttributeMaxDynamicSharedMemorySize, SMEM_BYTES);
    gru_persistent<<<BGN * HGN, NTHR, SMEM_BYTES>>>(
        x, Wx0, bx0, Wh0, bh0, Wx1, bx1, Wh1, bh1, Wo, bo, out);
}